// round 8
// baseline (speedup 1.0000x reference)
#include <cuda_runtime.h>
#include <float.h>

// AttentionSelector (R8 = R6 + vectorized 128-bit memory ops).
//  CTA = 8 consecutive bags = contiguous row span. Rows are 2760B, so only
//  even rows are 16B-aligned; odd rows handled via shifted windows (P1) or
//  float2 pairs at identical positions (P3/P4).
//  P1: warp per row; x float4 in aligned window [s,s+688), rel float4 if same
//      parity else float2 pairs; 2-elem remainder on lane 0.
//  P2: warp w softmax for bag w in smem.
//  P3: warp w streams its bag rows; fixed lane->position map (4k..4k+3),
//      even rows LDG.128, odd rows 2x LDG.64; att as float4 regs.
//  P4: att staged as padded float4 in smem (LDS.128); rel float4 for even r;
//      7 rel rows x 8 bags per warp, split (4 bags)x(4+3 rows) for regs.
// scope/labels are int32 on device (JAX x64-disabled downgrades int64).

static constexpr int Dd    = 690;
static constexpr int RR    = 53;
static constexpr int NT    = 256;
static constexpr int NW    = 8;     // warps = bags per CTA
static constexpr int NC4   = 6;     // float4 chunks: k=c*32+lane, k<=172
static constexpr int K4MAX = 172;   // full float4 groups (688 elements)
static constexpr int SP4   = 192;   // s_att4 bag stride in float4
static constexpr int RPW   = 7;     // rel rows per warp in P4
static constexpr int CAP   = 512;   // max rows per span (fallback below)

__device__ __forceinline__ float wsum(float v) {
#pragma unroll
    for (int o = 16; o; o >>= 1) v += __shfl_xor_sync(0xffffffffu, v, o);
    return v;
}
__device__ __forceinline__ float wmax(float v) {
#pragma unroll
    for (int o = 16; o; o >>= 1) v = fmaxf(v, __shfl_xor_sync(0xffffffffu, v, o));
    return v;
}

// both sides 16B-aligned float4 (same parity, shifted window)
__device__ __forceinline__ float dot44(const float4* __restrict__ xp,
                                       const float4* __restrict__ yp, int lane) {
    float a0 = 0.f, a1 = 0.f;
#pragma unroll
    for (int c = 0; c < NC4; c++) {
        const int k = c * 32 + lane;
        if (k < K4MAX) {
            const float4 x = xp[k], y = yp[k];
            if (c & 1) {
                a1 = fmaf(x.x, y.x, a1); a1 = fmaf(x.y, y.y, a1);
                a1 = fmaf(x.z, y.z, a1); a1 = fmaf(x.w, y.w, a1);
            } else {
                a0 = fmaf(x.x, y.x, a0); a0 = fmaf(x.y, y.y, a0);
                a0 = fmaf(x.z, y.z, a0); a0 = fmaf(x.w, y.w, a0);
            }
        }
    }
    return a0 + a1;
}

// x float4 aligned, y (opposite parity) via float2 pairs at same elements
__device__ __forceinline__ float dot42(const float4* __restrict__ xp,
                                       const float2* __restrict__ yp2, int lane) {
    float a0 = 0.f, a1 = 0.f;
#pragma unroll
    for (int c = 0; c < NC4; c++) {
        const int k = c * 32 + lane;
        if (k < K4MAX) {
            const float4 x = xp[k];
            const float2 y0 = yp2[2 * k], y1 = yp2[2 * k + 1];
            if (c & 1) {
                a1 = fmaf(x.x, y0.x, a1); a1 = fmaf(x.y, y0.y, a1);
                a1 = fmaf(x.z, y1.x, a1); a1 = fmaf(x.w, y1.y, a1);
            } else {
                a0 = fmaf(x.x, y0.x, a0); a0 = fmaf(x.y, y0.y, a0);
                a0 = fmaf(x.z, y1.x, a0); a0 = fmaf(x.w, y1.y, a0);
            }
        }
    }
    return a0 + a1;
}

// float2 fallback dot (large-span path only)
__device__ __forceinline__ float dot_f2(const float2* __restrict__ rp,
                                        const float2* __restrict__ lp, int lane) {
    float pa0 = 0.f, pa1 = 0.f;
#pragma unroll
    for (int c = 0; c < 11; c++) {
        const int k = c * 32 + lane;
        if (k < 345) {
            const float2 x = rp[k], y = lp[k];
            if (c & 1) { pa1 = fmaf(x.x, y.x, pa1); pa1 = fmaf(x.y, y.y, pa1); }
            else       { pa0 = fmaf(x.x, y.x, pa0); pa0 = fmaf(x.y, y.y, pa0); }
        }
    }
    return pa0 + pa1;
}

__global__ __launch_bounds__(NT, 4) void bag_kernel(
    const float* __restrict__ repre,
    const float* __restrict__ rel,
    const float* __restrict__ bias,
    const int*   __restrict__ scope,
    const int*   __restrict__ labels,
    float* __restrict__ out)
{
    __shared__ float s_log[CAP];
    __shared__ __align__(16) float4 s_att4[NW * SP4];  // 24 KB

    const int tid  = threadIdx.x;
    const int lane = tid & 31;
    const int wid  = tid >> 5;
    const int bag0 = blockIdx.x * NW;
    const int bag  = bag0 + wid;

    const int start = scope[2 * bag];
    const int end   = scope[2 * bag + 1];
    const int row0  = scope[2 * bag0];
    const int row1  = scope[2 * (bag0 + NW - 1) + 1];

    if (row1 - row0 <= CAP) {
        // ---- P1: logits for span rows (warp per row, vectorized) ----
        for (int i = row0 + wid; i < row1; i += NW) {
            const int lab = labels[i];
            const float* xr = repre + i * Dd;
            const float* yr = rel + lab * Dd;
            const int sx = (i & 1) << 1;               // 0 or 2
            float acc;
            if (((lab ^ i) & 1) == 0)
                acc = dot44(reinterpret_cast<const float4*>(xr + sx),
                            reinterpret_cast<const float4*>(yr + sx), lane);
            else
                acc = dot42(reinterpret_cast<const float4*>(xr + sx),
                            reinterpret_cast<const float2*>(yr + sx), lane);
            if (lane == 0) {                           // 2-element remainder
                const int le = sx ? 0 : 688;
                const float2 xa = *reinterpret_cast<const float2*>(xr + le);
                const float2 yb = *reinterpret_cast<const float2*>(yr + le);
                acc += xa.x * yb.x + xa.y * yb.y;
            }
            acc = wsum(acc);
            if (lane == 0) s_log[i - row0] = acc;
        }
        __syncthreads();

        // ---- P2: softmax for own bag ----
        const int n   = end - start;
        const int off = start - row0;
        float tm = -FLT_MAX;
        for (int j = lane; j < n; j += 32) tm = fmaxf(tm, s_log[off + j]);
        tm = wmax(tm);
        float ps = 0.f;
        for (int j = lane; j < n; j += 32) {
            const float e = __expf(s_log[off + j] - tm);
            s_log[off + j] = e;
            ps += e;
        }
        ps = wsum(ps);
        const float inv = 1.0f / ps;
        __syncwarp();

        // ---- P3: weighted pool of own bag (fixed position map 4k..4k+3) ----
        float4 att[NC4];
#pragma unroll
        for (int c = 0; c < NC4; c++) att[c] = make_float4(0.f, 0.f, 0.f, 0.f);

        for (int r = 0; r < n; r++) {
            const int row = start + r;
            const float w = s_log[off + r];
            if ((row & 1) == 0) {
                const float4* xp4 = reinterpret_cast<const float4*>(repre + row * Dd);
#pragma unroll
                for (int c = 0; c < NC4; c++) {
                    const int k = c * 32 + lane;
                    if (k < K4MAX) {
                        const float4 x = xp4[k];
                        att[c].x = fmaf(w, x.x, att[c].x);
                        att[c].y = fmaf(w, x.y, att[c].y);
                        att[c].z = fmaf(w, x.z, att[c].z);
                        att[c].w = fmaf(w, x.w, att[c].w);
                    } else if (k == K4MAX) {
                        const float2 t = reinterpret_cast<const float2*>(xp4)[344];
                        att[c].x = fmaf(w, t.x, att[c].x);
                        att[c].y = fmaf(w, t.y, att[c].y);
                    }
                }
            } else {
                const float2* xp2 = reinterpret_cast<const float2*>(repre + row * Dd);
#pragma unroll
                for (int c = 0; c < NC4; c++) {
                    const int k = c * 32 + lane;
                    if (k < K4MAX) {
                        const float2 t0 = xp2[2 * k], t1 = xp2[2 * k + 1];
                        att[c].x = fmaf(w, t0.x, att[c].x);
                        att[c].y = fmaf(w, t0.y, att[c].y);
                        att[c].z = fmaf(w, t1.x, att[c].z);
                        att[c].w = fmaf(w, t1.y, att[c].w);
                    } else if (k == K4MAX) {
                        const float2 t = xp2[344];
                        att[c].x = fmaf(w, t.x, att[c].x);
                        att[c].y = fmaf(w, t.y, att[c].y);
                    }
                }
            }
        }
        // normalize + store (zero padding beyond k=172)
#pragma unroll
        for (int c = 0; c < NC4; c++) {
            const int k = c * 32 + lane;
            float4 v = make_float4(0.f, 0.f, 0.f, 0.f);
            if (k <= K4MAX)
                v = make_float4(att[c].x * inv, att[c].y * inv,
                                att[c].z * inv, att[c].w * inv);
            s_att4[wid * SP4 + k] = v;
        }
    } else {
        // ---- fallback for giant spans (block-uniform; correctness only) ----
        float tm = -FLT_MAX;
        for (int i = start; i < end; i++) {
            const float2* rp = reinterpret_cast<const float2*>(repre + i * Dd);
            const float2* lp = reinterpret_cast<const float2*>(rel + labels[i] * Dd);
            tm = fmaxf(tm, wsum(dot_f2(rp, lp, lane)));
        }
        float4 att[NC4];
#pragma unroll
        for (int c = 0; c < NC4; c++) att[c] = make_float4(0.f, 0.f, 0.f, 0.f);
        float s = 0.f;
        for (int i = start; i < end; i++) {
            const float2* rp = reinterpret_cast<const float2*>(repre + i * Dd);
            const float2* lp = reinterpret_cast<const float2*>(rel + labels[i] * Dd);
            const float e = __expf(wsum(dot_f2(rp, lp, lane)) - tm);
            s += e;
#pragma unroll
            for (int c = 0; c < NC4; c++) {
                const int k = c * 32 + lane;
                if (k < K4MAX) {
                    const float2 t0 = rp[2 * k], t1 = rp[2 * k + 1];
                    att[c].x = fmaf(e, t0.x, att[c].x);
                    att[c].y = fmaf(e, t0.y, att[c].y);
                    att[c].z = fmaf(e, t1.x, att[c].z);
                    att[c].w = fmaf(e, t1.y, att[c].w);
                } else if (k == K4MAX) {
                    const float2 t = rp[344];
                    att[c].x = fmaf(e, t.x, att[c].x);
                    att[c].y = fmaf(e, t.y, att[c].y);
                }
            }
        }
        const float inv = 1.0f / s;
#pragma unroll
        for (int c = 0; c < NC4; c++) {
            const int k = c * 32 + lane;
            float4 v = make_float4(0.f, 0.f, 0.f, 0.f);
            if (k <= K4MAX)
                v = make_float4(att[c].x * inv, att[c].y * inv,
                                att[c].z * inv, att[c].w * inv);
            s_att4[wid * SP4 + k] = v;
        }
    }
    __syncthreads();

    // ---- P4: out[bag][r] = dot(att[bag], rel[r]) + bias[r]
    //      warp owns 7 rel rows; bags split 4+4, rows split 4+3 (reg cap) ----
    const int r0w = wid * RPW;
#pragma unroll
    for (int half = 0; half < 2; half++) {
        const int bbase = half * 4;
#pragma unroll
        for (int g = 0; g < 2; g++) {
            const int jb = g ? 4 : 0;
            const int jn = g ? 3 : 4;
            float acc4[4][4];
#pragma unroll
            for (int j = 0; j < 4; j++)
#pragma unroll
                for (int b = 0; b < 4; b++) acc4[j][b] = 0.f;

            for (int c = 0; c < NC4; c++) {
                const int k = c * 32 + lane;
                float4 a[4];
#pragma unroll
                for (int b = 0; b < 4; b++)
                    a[b] = s_att4[(bbase + b) * SP4 + k];
#pragma unroll
                for (int j = 0; j < 4; j++) {
                    if (j >= jn) break;
                    const int rr = r0w + jb + j;
                    float4 rv = make_float4(0.f, 0.f, 0.f, 0.f);
                    if (rr < RR) {
                        if ((rr & 1) == 0) {
                            const float4* yp4 = reinterpret_cast<const float4*>(rel + rr * Dd);
                            if (k < K4MAX) rv = yp4[k];
                            else if (k == K4MAX) {
                                const float2 t = reinterpret_cast<const float2*>(yp4)[344];
                                rv.x = t.x; rv.y = t.y;
                            }
                        } else {
                            const float2* yp2 = reinterpret_cast<const float2*>(rel + rr * Dd);
                            if (k < K4MAX) {
                                const float2 t0 = yp2[2 * k], t1 = yp2[2 * k + 1];
                                rv = make_float4(t0.x, t0.y, t1.x, t1.y);
                            } else if (k == K4MAX) {
                                const float2 t = yp2[344];
                                rv.x = t.x; rv.y = t.y;
                            }
                        }
                    }
#pragma unroll
                    for (int b = 0; b < 4; b++) {
                        acc4[j][b] = fmaf(rv.x, a[b].x, acc4[j][b]);
                        acc4[j][b] = fmaf(rv.y, a[b].y, acc4[j][b]);
                        acc4[j][b] = fmaf(rv.z, a[b].z, acc4[j][b]);
                        acc4[j][b] = fmaf(rv.w, a[b].w, acc4[j][b]);
                    }
                }
            }
#pragma unroll
            for (int j = 0; j < 4; j++) {
                if (j >= jn) break;
                const int rr = r0w + jb + j;
#pragma unroll
                for (int b = 0; b < 4; b++) {
                    const float v = wsum(acc4[j][b]);
                    if (lane == 0 && rr < RR)
                        out[(bag0 + bbase + b) * RR + rr] = v + bias[rr];
                }
            }
        }
    }
}

extern "C" void kernel_launch(void* const* d_in, const int* in_sizes, int n_in,
                              void* d_out, int out_size) {
    const float* repre  = (const float*)d_in[0];
    const float* rel    = (const float*)d_in[1];
    const float* bias   = (const float*)d_in[2];
    const int*   scope  = (const int*)d_in[3];
    const int*   labels = (const int*)d_in[4];
    float* out = (float*)d_out;

    const int num_bags = in_sizes[3] / 2;   // 25000
    const int grid = num_bags / NW;         // 3125 (exact)
    bag_kernel<<<grid, NT>>>(repre, rel, bias, scope, labels, out);
}

// round 9
// speedup vs baseline: 1.2435x; 1.2435x over previous
#include <cuda_runtime.h>
#include <float.h>

// AttentionSelector (R9 = R6 + 5 CTAs/SM occupancy push).
//  CTA = 8 consecutive bags = contiguous row span.
//  P1: warps stride over span rows, 2 rows/iter, split accs -> logits to smem
//  P2: warp w softmax for bag w in smem
//  P3: warp w streams its bag rows (2/iter) -> att in regs, no reduces
//  P4: register-tiled micro-GEMM, bags split 4+4, rows split 4+3 (regs <=48)
// scope/labels are int32 on device (JAX x64-disabled downgrades int64).

static constexpr int Dd  = 690;
static constexpr int F2  = 345;   // float2 per row
static constexpr int NCH = 11;    // ceil(345/32) float2-chunks per lane
static constexpr int RR  = 53;
static constexpr int NT  = 256;
static constexpr int NW  = 8;     // warps = bags per CTA
static constexpr int SP2 = 352;   // s_att2 row stride in float2
static constexpr int RPW = 7;     // rel rows per warp in P4
static constexpr int CAP = 512;   // max rows per CTA span (fallback below)

__device__ __forceinline__ float wsum(float v) {
#pragma unroll
    for (int o = 16; o; o >>= 1) v += __shfl_xor_sync(0xffffffffu, v, o);
    return v;
}
__device__ __forceinline__ float wmax(float v) {
#pragma unroll
    for (int o = 16; o; o >>= 1) v = fmaxf(v, __shfl_xor_sync(0xffffffffu, v, o));
    return v;
}

__device__ __forceinline__ float dot_row(const float2* __restrict__ rp,
                                         const float2* __restrict__ lp,
                                         int lane) {
    float pa0 = 0.f, pa1 = 0.f;
#pragma unroll
    for (int c = 0; c < NCH; c++) {
        const int k = c * 32 + lane;
        if (k < F2) {
            const float2 x = rp[k], y = lp[k];
            if (c & 1) { pa1 = fmaf(x.x, y.x, pa1); pa1 = fmaf(x.y, y.y, pa1); }
            else       { pa0 = fmaf(x.x, y.x, pa0); pa0 = fmaf(x.y, y.y, pa0); }
        }
    }
    return pa0 + pa1;
}

__global__ __launch_bounds__(NT, 5) void bag_kernel(
    const float* __restrict__ repre,
    const float* __restrict__ rel,
    const float* __restrict__ bias,
    const int*   __restrict__ scope,
    const int*   __restrict__ labels,
    float* __restrict__ out)
{
    __shared__ float  s_log[CAP];
    __shared__ __align__(16) float2 s_att2[NW * SP2];  // 22.5 KB

    const int tid  = threadIdx.x;
    const int lane = tid & 31;
    const int wid  = tid >> 5;
    const int bag0 = blockIdx.x * NW;
    const int bag  = bag0 + wid;

    const int start = scope[2 * bag];
    const int end   = scope[2 * bag + 1];
    const int row0  = scope[2 * bag0];
    const int row1  = scope[2 * (bag0 + NW - 1) + 1];

    if (row1 - row0 <= CAP) {
        // ---- P1: logits for span rows, warp-strided, 2 rows per iteration ----
        int i = row0 + wid;
        for (; i + NW < row1; i += 2 * NW) {
            const int i2 = i + NW;
            const float2* rp0 = reinterpret_cast<const float2*>(repre + i  * Dd);
            const float2* lp0 = reinterpret_cast<const float2*>(rel + labels[i]  * Dd);
            const float2* rp1 = reinterpret_cast<const float2*>(repre + i2 * Dd);
            const float2* lp1 = reinterpret_cast<const float2*>(rel + labels[i2] * Dd);
            float a0 = 0.f, a1 = 0.f, b0 = 0.f, b1 = 0.f;
#pragma unroll
            for (int c = 0; c < NCH; c++) {
                const int k = c * 32 + lane;
                if (k < F2) {
                    const float2 x0 = rp0[k], y0 = lp0[k];
                    const float2 x1 = rp1[k], y1 = lp1[k];
                    if (c & 1) {
                        a1 = fmaf(x0.x, y0.x, a1); a1 = fmaf(x0.y, y0.y, a1);
                        b1 = fmaf(x1.x, y1.x, b1); b1 = fmaf(x1.y, y1.y, b1);
                    } else {
                        a0 = fmaf(x0.x, y0.x, a0); a0 = fmaf(x0.y, y0.y, a0);
                        b0 = fmaf(x1.x, y1.x, b0); b0 = fmaf(x1.y, y1.y, b0);
                    }
                }
            }
            float accA = a0 + a1;
            float accB = b0 + b1;
#pragma unroll
            for (int o = 16; o; o >>= 1) {
                accA += __shfl_xor_sync(0xffffffffu, accA, o);
                accB += __shfl_xor_sync(0xffffffffu, accB, o);
            }
            if (lane == 0) { s_log[i - row0] = accA; s_log[i2 - row0] = accB; }
        }
        if (i < row1) {
            const float2* rp = reinterpret_cast<const float2*>(repre + i * Dd);
            const float2* lp = reinterpret_cast<const float2*>(rel + labels[i] * Dd);
            const float acc = wsum(dot_row(rp, lp, lane));
            if (lane == 0) s_log[i - row0] = acc;
        }
        __syncthreads();

        // ---- P2: softmax for own bag ----
        const int n   = end - start;
        const int off = start - row0;
        float tm = -FLT_MAX;
        for (int j = lane; j < n; j += 32) tm = fmaxf(tm, s_log[off + j]);
        tm = wmax(tm);
        float ps = 0.f;
        for (int j = lane; j < n; j += 32) {
            const float e = __expf(s_log[off + j] - tm);
            s_log[off + j] = e;
            ps += e;
        }
        ps = wsum(ps);
        const float inv = 1.0f / ps;
        __syncwarp();

        // ---- P3: weighted pool of own bag (2 rows/iter, no reduces) ----
        float2 att[NCH];
#pragma unroll
        for (int c = 0; c < NCH; c++) att[c] = make_float2(0.f, 0.f);
        int r = 0;
        for (; r + 2 <= n; r += 2) {
            const float w0 = s_log[off + r];
            const float w1 = s_log[off + r + 1];
            const float2* rp0 = reinterpret_cast<const float2*>(repre + (start + r)     * Dd);
            const float2* rp1 = reinterpret_cast<const float2*>(repre + (start + r + 1) * Dd);
#pragma unroll
            for (int c = 0; c < NCH; c++) {
                const int k = c * 32 + lane;
                if (k < F2) {
                    const float2 x0 = rp0[k], x1 = rp1[k];
                    att[c].x = fmaf(w0, x0.x, att[c].x);
                    att[c].y = fmaf(w0, x0.y, att[c].y);
                    att[c].x = fmaf(w1, x1.x, att[c].x);
                    att[c].y = fmaf(w1, x1.y, att[c].y);
                }
            }
        }
        if (r < n) {
            const float w = s_log[off + r];
            const float2* rp = reinterpret_cast<const float2*>(repre + (start + r) * Dd);
#pragma unroll
            for (int c = 0; c < NCH; c++) {
                const int k = c * 32 + lane;
                if (k < F2) {
                    const float2 x = rp[k];
                    att[c].x = fmaf(w, x.x, att[c].x);
                    att[c].y = fmaf(w, x.y, att[c].y);
                }
            }
        }
#pragma unroll
        for (int c = 0; c < NCH; c++) {
            const int k = c * 32 + lane;
            if (k < F2) s_att2[wid * SP2 + k] = make_float2(att[c].x * inv, att[c].y * inv);
        }
    } else {
        // ---- fallback for giant spans (block-uniform branch; correct) ----
        float tm = -FLT_MAX;
        for (int i = start; i < end; i++) {
            const float2* rp = reinterpret_cast<const float2*>(repre + i * Dd);
            const float2* lp = reinterpret_cast<const float2*>(rel + labels[i] * Dd);
            tm = fmaxf(tm, wsum(dot_row(rp, lp, lane)));
        }
        float2 att[NCH];
#pragma unroll
        for (int c = 0; c < NCH; c++) att[c] = make_float2(0.f, 0.f);
        float s = 0.f;
        for (int i = start; i < end; i++) {
            const float2* rp = reinterpret_cast<const float2*>(repre + i * Dd);
            const float2* lp = reinterpret_cast<const float2*>(rel + labels[i] * Dd);
            const float e = __expf(wsum(dot_row(rp, lp, lane)) - tm);
            s += e;
#pragma unroll
            for (int c = 0; c < NCH; c++) {
                const int k = c * 32 + lane;
                if (k < F2) {
                    const float2 x = rp[k];
                    att[c].x = fmaf(e, x.x, att[c].x);
                    att[c].y = fmaf(e, x.y, att[c].y);
                }
            }
        }
        const float inv = 1.0f / s;
#pragma unroll
        for (int c = 0; c < NCH; c++) {
            const int k = c * 32 + lane;
            if (k < F2) s_att2[wid * SP2 + k] = make_float2(att[c].x * inv, att[c].y * inv);
        }
    }
    __syncthreads();

    // ---- P4: out[bag][r] = dot(att[bag], rel[r]) + bias[r]
    //      warp owns 7 rel rows; bags split 4+4, rows split 4+3 (reg cap) ----
    const int r0w = wid * RPW;
#pragma unroll
    for (int half = 0; half < 2; half++) {
        const int bbase = half * 4;
#pragma unroll
        for (int g = 0; g < 2; g++) {
            const int jb = g ? 4 : 0;
            const int jn = g ? 3 : 4;
            float acc4[4][4];
#pragma unroll
            for (int j = 0; j < 4; j++)
#pragma unroll
                for (int b = 0; b < 4; b++) acc4[j][b] = 0.f;

            for (int c = 0; c < NCH; c++) {
                const int k = c * 32 + lane;
                const bool v = (k < F2);
                float2 a[4];
#pragma unroll
                for (int b = 0; b < 4; b++)
                    a[b] = v ? s_att2[(bbase + b) * SP2 + k] : make_float2(0.f, 0.f);
#pragma unroll
                for (int j = 0; j < 4; j++) {
                    if (j >= jn) break;
                    const int rr = r0w + jb + j;
                    float2 rv = make_float2(0.f, 0.f);
                    if (v && rr < RR)
                        rv = reinterpret_cast<const float2*>(rel)[rr * F2 + k];
#pragma unroll
                    for (int b = 0; b < 4; b++) {
                        acc4[j][b] = fmaf(rv.x, a[b].x, acc4[j][b]);
                        acc4[j][b] = fmaf(rv.y, a[b].y, acc4[j][b]);
                    }
                }
            }
#pragma unroll
            for (int j = 0; j < 4; j++) {
                if (j >= jn) break;
                const int rr = r0w + jb + j;
#pragma unroll
                for (int b = 0; b < 4; b++) {
                    const float v = wsum(acc4[j][b]);
                    if (lane == 0 && rr < RR)
                        out[(bag0 + bbase + b) * RR + rr] = v + bias[rr];
                }
            }
        }
    }
}

extern "C" void kernel_launch(void* const* d_in, const int* in_sizes, int n_in,
                              void* d_out, int out_size) {
    const float* repre  = (const float*)d_in[0];
    const float* rel    = (const float*)d_in[1];
    const float* bias   = (const float*)d_in[2];
    const int*   scope  = (const int*)d_in[3];
    const int*   labels = (const int*)d_in[4];
    float* out = (float*)d_out;

    const int num_bags = in_sizes[3] / 2;   // 25000
    const int grid = num_bags / NW;         // 3125 (exact)
    bag_kernel<<<grid, NT>>>(repre, rel, bias, scope, labels, out);
}